// round 6
// baseline (speedup 1.0000x reference)
#include <cuda_runtime.h>
#include <cuda_fp16.h>
#include <mma.h>
using namespace nvcuda;

#define N_NODES   100000
#define N_EDGES   1280000
#define D         64
#define N_GRAPHS  512
#define SCAN_B    1024
#define N_SCANBLK ((N_NODES + SCAN_B - 1) / SCAN_B)   // 98

// ---------------- scratch (device globals; no cudaMalloc allowed) -----------
__device__ __half g_h  [N_NODES * D];   // GEMM output, pre-scaled by dinv[row]
__device__ __half g_t0 [N_NODES * D];
__device__ __half g_t1 [N_NODES * D];
__device__ float  g_dinv[N_NODES];
__device__ int    g_dege[N_NODES];
__device__ int    g_rowstart[N_NODES + 1];
__device__ int    g_cursor[N_NODES];
__device__ int    g_bsums[128];
__device__ int    g_csrc [N_EDGES];
__device__ float  g_nodedot[N_NODES];

// ---------------- setup kernels ---------------------------------------------
__global__ void k_deg(const int* __restrict__ ei) {
    int t = blockIdx.x * blockDim.x + threadIdx.x;
    if (t < N_EDGES / 4) {
        int4 d4 = ((const int4*)(ei + N_EDGES))[t];
        atomicAdd(&g_dege[d4.x], 1);
        atomicAdd(&g_dege[d4.y], 1);
        atomicAdd(&g_dege[d4.z], 1);
        atomicAdd(&g_dege[d4.w], 1);
    }
}

__global__ void k_scan1() {
    __shared__ int sh[SCAN_B];
    int tid = threadIdx.x;
    int i = blockIdx.x * SCAN_B + tid;
    int v = (i < N_NODES) ? g_dege[i] : 0;
    sh[tid] = v;
    __syncthreads();
    for (int off = 1; off < SCAN_B; off <<= 1) {
        int t = 0;
        if (tid >= off) t = sh[tid - off];
        __syncthreads();
        sh[tid] += t;
        __syncthreads();
    }
    int incl = sh[tid];
    if (i < N_NODES) g_rowstart[i] = incl - v;   // exclusive
    if (tid == SCAN_B - 1) g_bsums[blockIdx.x] = incl;
}

__global__ void k_scan2() {
    __shared__ int sh[128];
    int tid = threadIdx.x;
    int v = (tid < N_SCANBLK) ? g_bsums[tid] : 0;
    sh[tid] = v;
    __syncthreads();
    for (int off = 1; off < 128; off <<= 1) {
        int t = 0;
        if (tid >= off) t = sh[tid - off];
        __syncthreads();
        sh[tid] += t;
        __syncthreads();
    }
    if (tid < N_SCANBLK) g_bsums[tid] = sh[tid] - v;   // exclusive
    if (tid == N_SCANBLK - 1) g_rowstart[N_NODES] = sh[tid];
}

__global__ void k_scan3() {
    int i = blockIdx.x * blockDim.x + threadIdx.x;
    if (i < N_NODES) {
        int rs = g_rowstart[i] + g_bsums[i / SCAN_B];
        g_rowstart[i] = rs;
        g_cursor[i] = rs;
        g_dinv[i] = rsqrtf((float)(g_dege[i] + 1));   // +1 self loop
    }
}

__global__ void k_fill(const int* __restrict__ ei) {
    int t = blockIdx.x * blockDim.x + threadIdx.x;
    if (t < N_EDGES / 4) {
        int4 s4 = ((const int4*)ei)[t];
        int4 d4 = ((const int4*)(ei + N_EDGES))[t];
        g_csrc[atomicAdd(&g_cursor[d4.x], 1)] = s4.x;
        g_csrc[atomicAdd(&g_cursor[d4.y], 1)] = s4.y;
        g_csrc[atomicAdd(&g_cursor[d4.z], 1)] = s4.z;
        g_csrc[atomicAdd(&g_cursor[d4.w], 1)] = s4.w;
    }
}

// ---------------- tensor-core GEMM: out[row] = dinv[row]*(in[row] @ W), fp16 out
#define LDW 72   // padded leading dim to dodge smem bank conflicts

__device__ __forceinline__ void load_weights_sh(__half* wsh, const float* __restrict__ W, int tid) {
    for (int i = tid; i < D * D; i += 128) {
        int r = i >> 6, c = i & 63;
        wsh[r * LDW + c] = __float2half(W[i]);
    }
}

__device__ __forceinline__ void gemm_epilogue(const float* osh, __half* __restrict__ out,
                                              int blockRow0, int tid) {
    int r = tid >> 1;
    int cbase = (tid & 1) * 32;
    int row = blockRow0 + r;
    if (row >= N_NODES) return;
    float s = g_dinv[row];
    uint4* orow = (uint4*)(out + (size_t)row * D + cbase);
    const float* src = osh + r * LDW + cbase;
#pragma unroll
    for (int q = 0; q < 4; q++) {
        __half2 p0 = __floats2half2_rn(src[q * 8 + 0] * s, src[q * 8 + 1] * s);
        __half2 p1 = __floats2half2_rn(src[q * 8 + 2] * s, src[q * 8 + 3] * s);
        __half2 p2 = __floats2half2_rn(src[q * 8 + 4] * s, src[q * 8 + 5] * s);
        __half2 p3 = __floats2half2_rn(src[q * 8 + 6] * s, src[q * 8 + 7] * s);
        uint4 u;
        u.x = *(unsigned*)&p0; u.y = *(unsigned*)&p1;
        u.z = *(unsigned*)&p2; u.w = *(unsigned*)&p3;
        orow[q] = u;
    }
}

__global__ void __launch_bounds__(128) k_gemm_f16(const __half* __restrict__ in,
                                                  const float* __restrict__ W,
                                                  __half* __restrict__ out) {
    __shared__ __half wsh[D * LDW];
    __shared__ float  osh[D * LDW];
    int tid = threadIdx.x;
    load_weights_sh(wsh, W, tid);
    __syncthreads();

    int warp = tid >> 5;
    int row0 = blockIdx.x * 64 + warp * 16;
    if (row0 < N_NODES) {
        wmma::fragment<wmma::accumulator, 16, 16, 16, float> acc[4];
#pragma unroll
        for (int n = 0; n < 4; n++) wmma::fill_fragment(acc[n], 0.0f);
#pragma unroll
        for (int k = 0; k < 4; k++) {
            wmma::fragment<wmma::matrix_a, 16, 16, 16, __half, wmma::row_major> a;
            wmma::load_matrix_sync(a, in + (size_t)row0 * D + k * 16, D);
#pragma unroll
            for (int n = 0; n < 4; n++) {
                wmma::fragment<wmma::matrix_b, 16, 16, 16, __half, wmma::row_major> b;
                wmma::load_matrix_sync(b, wsh + (k * 16) * LDW + n * 16, LDW);
                wmma::mma_sync(acc[n], a, b, acc[n]);
            }
        }
#pragma unroll
        for (int n = 0; n < 4; n++)
            wmma::store_matrix_sync(osh + (warp * 16) * LDW + n * 16, acc[n], LDW, wmma::mem_row_major);
    }
    __syncthreads();
    gemm_epilogue(osh, out, blockIdx.x * 64, tid);
}

__global__ void __launch_bounds__(128) k_gemm_f32(const float* __restrict__ in,
                                                  const float* __restrict__ W,
                                                  __half* __restrict__ out) {
    __shared__ __half wsh[D * LDW];
    __shared__ __half ash[D * LDW];
    __shared__ float  osh[D * LDW];
    int tid = threadIdx.x;
    load_weights_sh(wsh, W, tid);
    for (int i = tid; i < D * D; i += 128) {
        int r = i >> 6, c = i & 63;
        int row = blockIdx.x * 64 + r;
        float v = (row < N_NODES) ? in[(size_t)row * D + c] : 0.f;
        ash[r * LDW + c] = __float2half(v);
    }
    __syncthreads();

    int warp = tid >> 5;
    int row0 = blockIdx.x * 64 + warp * 16;
    if (row0 < N_NODES) {
        wmma::fragment<wmma::accumulator, 16, 16, 16, float> acc[4];
#pragma unroll
        for (int n = 0; n < 4; n++) wmma::fill_fragment(acc[n], 0.0f);
#pragma unroll
        for (int k = 0; k < 4; k++) {
            wmma::fragment<wmma::matrix_a, 16, 16, 16, __half, wmma::row_major> a;
            wmma::load_matrix_sync(a, ash + (warp * 16) * LDW + k * 16, LDW);
#pragma unroll
            for (int n = 0; n < 4; n++) {
                wmma::fragment<wmma::matrix_b, 16, 16, 16, __half, wmma::row_major> b;
                wmma::load_matrix_sync(b, wsh + (k * 16) * LDW + n * 16, LDW);
                wmma::mma_sync(acc[n], a, b, acc[n]);
            }
        }
#pragma unroll
        for (int n = 0; n < 4; n++)
            wmma::store_matrix_sync(osh + (warp * 16) * LDW + n * 16, acc[n], LDW, wmma::mem_row_major);
    }
    __syncthreads();
    gemm_epilogue(osh, out, blockIdx.x * 64, tid);
}

// ------- gather v2: 8 lanes/node, LDG.128 data, shfl-broadcast indices ------
// out_n = relu( dinv_n * (sum_{e:dst=n} h'[src_e] + h'[n]) + b )
// N_NODES*8 = 800000 divides 256 exactly -> no inactive lanes.
// IMPORTANT: shuffles inside the degree loop use a PER-GROUP mask, because the
// four 8-lane groups of a warp have different trip counts (different nodes).

__device__ __forceinline__ void acc8_add(float acc[8], float4 raw) {
    __half2* hp = (__half2*)&raw;
#pragma unroll
    for (int q = 0; q < 4; q++) {
        float2 f = __half22float2(hp[q]);
        acc[2 * q + 0] += f.x;
        acc[2 * q + 1] += f.y;
    }
}

template <bool FUSE_POOL>
__global__ void __launch_bounds__(256) k_gather8(const __half* __restrict__ h,
                                                 const float* __restrict__ b,
                                                 __half* __restrict__ out,
                                                 const float* __restrict__ fcw) {
    int gt = blockIdx.x * blockDim.x + threadIdx.x;
    int node = gt >> 3;
    int c = gt & 7;          // this lane's 8-channel group (16 bytes)
    int lane = threadIdx.x & 31;
    unsigned gmask = 0xffu << (lane & 24);   // the 8 lanes of my group

    const float4* h4 = (const float4*)h;   // 8 float4 per row

    float acc[8];
    {
        float4 raw = h4[(size_t)node * 8 + c];   // self loop (pre-scaled)
        __half2* hp = (__half2*)&raw;
#pragma unroll
        for (int q = 0; q < 4; q++) {
            float2 f = __half22float2(hp[q]);
            acc[2 * q + 0] = f.x;
            acc[2 * q + 1] = f.y;
        }
    }

    int e0 = g_rowstart[node];
    int e1 = g_rowstart[node + 1];
    for (int chunk = e0; chunk < e1; chunk += 8) {
        int t = chunk + c;
        int myidx = (t < e1) ? g_csrc[t] : 0;
        int m = e1 - chunk;
#pragma unroll
        for (int j = 0; j < 8; j++) {
            int s = __shfl_sync(gmask, myidx, j, 8);
            if (j < m) {
                float4 raw = h4[(size_t)s * 8 + c];
                acc8_add(acc, raw);
            }
        }
    }

    float di = g_dinv[node];
    float o[8];
    const float4* bb = (const float4*)(b + c * 8);
    float4 b0 = bb[0], b1 = bb[1];
    o[0] = fmaxf(acc[0] * di + b0.x, 0.f);
    o[1] = fmaxf(acc[1] * di + b0.y, 0.f);
    o[2] = fmaxf(acc[2] * di + b0.z, 0.f);
    o[3] = fmaxf(acc[3] * di + b0.w, 0.f);
    o[4] = fmaxf(acc[4] * di + b1.x, 0.f);
    o[5] = fmaxf(acc[5] * di + b1.y, 0.f);
    o[6] = fmaxf(acc[6] * di + b1.z, 0.f);
    o[7] = fmaxf(acc[7] * di + b1.w, 0.f);

    if (FUSE_POOL) {
        // dot with fc_w, reduce across the 8-lane group, write scalar per node
        const float4* ww = (const float4*)(fcw + c * 8);
        float4 w0 = ww[0], w1 = ww[1];
        float dot = o[0] * w0.x + o[1] * w0.y + o[2] * w0.z + o[3] * w0.w
                  + o[4] * w1.x + o[5] * w1.y + o[6] * w1.z + o[7] * w1.w;
#pragma unroll
        for (int off = 4; off > 0; off >>= 1)
            dot += __shfl_down_sync(0xffffffffu, dot, off, 8);
        if (c == 0) g_nodedot[node] = dot;
    } else {
        __half2 p0 = __floats2half2_rn(o[0], o[1]);
        __half2 p1 = __floats2half2_rn(o[2], o[3]);
        __half2 p2 = __floats2half2_rn(o[4], o[5]);
        __half2 p3 = __floats2half2_rn(o[6], o[7]);
        uint4 u;
        u.x = *(unsigned*)&p0; u.y = *(unsigned*)&p1;
        u.z = *(unsigned*)&p2; u.w = *(unsigned*)&p3;
        ((uint4*)out)[(size_t)node * 8 + c] = u;
    }
}

// ------- pool + head: one block per graph over per-node scalars --------------
__global__ void __launch_bounds__(256) k_pool_graph(const float* __restrict__ fcb,
                                                    const int* __restrict__ batch,
                                                    float* __restrict__ out) {
    __shared__ int bounds[2];
    __shared__ float red[256 / 32];
    int tid = threadIdx.x;
    int g = blockIdx.x;
    if (tid == 0 || tid == 1) {
        int key = g + tid;
        int lo = 0, hi = N_NODES;
        while (lo < hi) {
            int mid = (lo + hi) >> 1;
            if (batch[mid] < key) lo = mid + 1; else hi = mid;
        }
        bounds[tid] = lo;
    }
    __syncthreads();
    int start = bounds[0], end = bounds[1];

    float s = 0.f;
    for (int i = start + tid; i < end; i += 256) s += g_nodedot[i];
#pragma unroll
    for (int off = 16; off > 0; off >>= 1)
        s += __shfl_down_sync(0xffffffffu, s, off);
    if ((tid & 31) == 0) red[tid >> 5] = s;
    __syncthreads();
    if (tid == 0) {
        float tot = 0.f;
#pragma unroll
        for (int wi = 0; wi < 256 / 32; wi++) tot += red[wi];
        int cnt = end - start;
        out[g] = tot / fmaxf((float)cnt, 1.f) + fcb[0];
    }
}

// ---------------- launch ------------------------------------------------------
extern "C" void kernel_launch(void* const* d_in, const int* in_sizes, int n_in,
                              void* d_out, int out_size) {
    const float* x     = (const float*)d_in[0];
    const int*   ei    = (const int*)  d_in[1];
    const int*   batch = (const int*)  d_in[2];
    const float* w0    = (const float*)d_in[3];
    const float* b0    = (const float*)d_in[4];
    const float* w1    = (const float*)d_in[5];
    const float* b1    = (const float*)d_in[6];
    const float* w2    = (const float*)d_in[7];
    const float* b2    = (const float*)d_in[8];
    const float* fcw   = (const float*)d_in[9];
    const float* fcb   = (const float*)d_in[10];
    float* out = (float*)d_out;

    __half *h, *t0, *t1;
    void *p_dege;
    cudaGetSymbolAddress((void**)&h,  g_h);
    cudaGetSymbolAddress((void**)&t0, g_t0);
    cudaGetSymbolAddress((void**)&t1, g_t1);
    cudaGetSymbolAddress(&p_dege, g_dege);

    const int TB = 256;
    int nb_nodes = (N_NODES + TB - 1) / TB;           // 391
    int nb_edge4 = (N_EDGES / 4 + TB - 1) / TB;       // 1250
    int nb_gemm  = (N_NODES + 63) / 64;               // 1563
    int nb_gath  = (N_NODES * 8) / TB;                // 3125 exact

    cudaMemsetAsync(p_dege, 0, N_NODES * sizeof(int));

    // CSR build (once per call, reused by all 3 layers)
    k_deg  <<<nb_edge4, TB>>>(ei);
    k_scan1<<<N_SCANBLK, SCAN_B>>>();
    k_scan2<<<1, 128>>>();
    k_scan3<<<nb_nodes, TB>>>();
    k_fill <<<nb_edge4, TB>>>(ei);

    // layer 1
    k_gemm_f32<<<nb_gemm, 128>>>(x, w0, h);
    k_gather8<false><<<nb_gath, TB>>>(h, b0, t0, nullptr);
    // layer 2
    k_gemm_f16<<<nb_gemm, 128>>>(t0, w1, h);
    k_gather8<false><<<nb_gath, TB>>>(h, b1, t1, nullptr);
    // layer 3 (gather fused with pool dot; writes per-node scalar)
    k_gemm_f16<<<nb_gemm, 128>>>(t1, w2, h);
    k_gather8<true><<<nb_gath, TB>>>(h, b2, nullptr, fcw);

    // pool + head
    k_pool_graph<<<N_GRAPHS, 256>>>(fcb, batch, out);
}

// round 7
// speedup vs baseline: 1.0378x; 1.0378x over previous
#include <cuda_runtime.h>
#include <cuda_fp16.h>
#include <mma.h>
using namespace nvcuda;

#define N_NODES   100000
#define N_EDGES   1280000
#define D         64
#define N_GRAPHS  512
#define SCAN_B    1024
#define N_SCANBLK ((N_NODES + SCAN_B - 1) / SCAN_B)   // 98

// ---------------- scratch (device globals; no cudaMalloc allowed) -----------
__device__ __half g_h  [N_NODES * D];   // GEMM output, pre-scaled by dinv[row]
__device__ __half g_t0 [N_NODES * D];
__device__ __half g_t1 [N_NODES * D];
__device__ float  g_dinv[N_NODES];
__device__ int    g_dege[N_NODES];
__device__ int    g_rowstart[N_NODES + 1];
__device__ int    g_bsums[128];
__device__ int    g_csrc [N_EDGES];
__device__ int    g_rank [N_EDGES];
__device__ float  g_nodedot[N_NODES];

// ---------------- setup kernels ---------------------------------------------
// degree count; atomic return value = this edge's rank within its dst bucket
__global__ void k_deg(const int* __restrict__ ei) {
    int t = blockIdx.x * blockDim.x + threadIdx.x;
    if (t < N_EDGES / 4) {
        int4 d4 = ((const int4*)(ei + N_EDGES))[t];
        int4 r;
        r.x = atomicAdd(&g_dege[d4.x], 1);
        r.y = atomicAdd(&g_dege[d4.y], 1);
        r.z = atomicAdd(&g_dege[d4.z], 1);
        r.w = atomicAdd(&g_dege[d4.w], 1);
        ((int4*)g_rank)[t] = r;
    }
}

__global__ void k_scan1() {
    __shared__ int sh[SCAN_B];
    int tid = threadIdx.x;
    int i = blockIdx.x * SCAN_B + tid;
    int v = (i < N_NODES) ? g_dege[i] : 0;
    sh[tid] = v;
    __syncthreads();
    for (int off = 1; off < SCAN_B; off <<= 1) {
        int t = 0;
        if (tid >= off) t = sh[tid - off];
        __syncthreads();
        sh[tid] += t;
        __syncthreads();
    }
    int incl = sh[tid];
    if (i < N_NODES) g_rowstart[i] = incl - v;   // exclusive
    if (tid == SCAN_B - 1) g_bsums[blockIdx.x] = incl;
}

__global__ void k_scan2() {
    __shared__ int sh[128];
    int tid = threadIdx.x;
    int v = (tid < N_SCANBLK) ? g_bsums[tid] : 0;
    sh[tid] = v;
    __syncthreads();
    for (int off = 1; off < 128; off <<= 1) {
        int t = 0;
        if (tid >= off) t = sh[tid - off];
        __syncthreads();
        sh[tid] += t;
        __syncthreads();
    }
    if (tid < N_SCANBLK) g_bsums[tid] = sh[tid] - v;   // exclusive
    if (tid == N_SCANBLK - 1) g_rowstart[N_NODES] = sh[tid];
}

__global__ void k_scan3() {
    int i = blockIdx.x * blockDim.x + threadIdx.x;
    if (i < N_NODES) {
        g_rowstart[i] = g_rowstart[i] + g_bsums[i / SCAN_B];
        g_dinv[i] = rsqrtf((float)(g_dege[i] + 1));   // +1 self loop
    }
}

// atomic-free fill: pos = rowstart[dst] + rank[edge]
__global__ void k_fill(const int* __restrict__ ei) {
    int t = blockIdx.x * blockDim.x + threadIdx.x;
    if (t < N_EDGES / 4) {
        int4 s4 = ((const int4*)ei)[t];
        int4 d4 = ((const int4*)(ei + N_EDGES))[t];
        int4 r4 = ((const int4*)g_rank)[t];
        g_csrc[g_rowstart[d4.x] + r4.x] = s4.x;
        g_csrc[g_rowstart[d4.y] + r4.y] = s4.y;
        g_csrc[g_rowstart[d4.z] + r4.z] = s4.z;
        g_csrc[g_rowstart[d4.w] + r4.w] = s4.w;
    }
}

// ---------------- tensor-core GEMM: out[row] = dinv[row]*(in[row] @ W), fp16 out
#define LDW 72   // padded leading dim to dodge smem bank conflicts

__device__ __forceinline__ void gemm_epilogue(const float* osh, __half* __restrict__ out,
                                              int blockRow0, int tid) {
    int r = tid >> 1;
    int cbase = (tid & 1) * 32;
    int row = blockRow0 + r;
    if (row >= N_NODES) return;
    float s = g_dinv[row];
    uint4* orow = (uint4*)(out + (size_t)row * D + cbase);
    const float* src = osh + r * LDW + cbase;
#pragma unroll
    for (int q = 0; q < 4; q++) {
        __half2 p0 = __floats2half2_rn(src[q * 8 + 0] * s, src[q * 8 + 1] * s);
        __half2 p1 = __floats2half2_rn(src[q * 8 + 2] * s, src[q * 8 + 3] * s);
        __half2 p2 = __floats2half2_rn(src[q * 8 + 4] * s, src[q * 8 + 5] * s);
        __half2 p3 = __floats2half2_rn(src[q * 8 + 6] * s, src[q * 8 + 7] * s);
        uint4 u;
        u.x = *(unsigned*)&p0; u.y = *(unsigned*)&p1;
        u.z = *(unsigned*)&p2; u.w = *(unsigned*)&p3;
        orow[q] = u;
    }
}

// fp16-input GEMM: 256 threads, 128 rows per block
__global__ void __launch_bounds__(256) k_gemm_f16(const __half* __restrict__ in,
                                                  const float* __restrict__ W,
                                                  __half* __restrict__ out) {
    __shared__ __half wsh[D * LDW];        // 9216 B
    __shared__ float  osh[128 * LDW];      // 36864 B
    int tid = threadIdx.x;
    for (int i = tid; i < D * D; i += 256) {
        int r = i >> 6, c = i & 63;
        wsh[r * LDW + c] = __float2half(W[i]);
    }
    __syncthreads();

    int warp = tid >> 5;                   // 0..7
    int row0 = blockIdx.x * 128 + warp * 16;
    if (row0 < N_NODES) {
        wmma::fragment<wmma::accumulator, 16, 16, 16, float> acc[4];
#pragma unroll
        for (int n = 0; n < 4; n++) wmma::fill_fragment(acc[n], 0.0f);
#pragma unroll
        for (int k = 0; k < 4; k++) {
            wmma::fragment<wmma::matrix_a, 16, 16, 16, __half, wmma::row_major> a;
            wmma::load_matrix_sync(a, in + (size_t)row0 * D + k * 16, D);
#pragma unroll
            for (int n = 0; n < 4; n++) {
                wmma::fragment<wmma::matrix_b, 16, 16, 16, __half, wmma::row_major> b;
                wmma::load_matrix_sync(b, wsh + (k * 16) * LDW + n * 16, LDW);
                wmma::mma_sync(acc[n], a, b, acc[n]);
            }
        }
#pragma unroll
        for (int n = 0; n < 4; n++)
            wmma::store_matrix_sync(osh + (warp * 16) * LDW + n * 16, acc[n], LDW, wmma::mem_row_major);
    }
    __syncthreads();
    gemm_epilogue(osh, out, blockIdx.x * 128, tid);
}

// fp32-input GEMM (layer 1 only): 128 threads, 64 rows per block
__global__ void __launch_bounds__(128) k_gemm_f32(const float* __restrict__ in,
                                                  const float* __restrict__ W,
                                                  __half* __restrict__ out) {
    __shared__ __half wsh[D * LDW];
    __shared__ __half ash[D * LDW];
    __shared__ float  osh[D * LDW];
    int tid = threadIdx.x;
    for (int i = tid; i < D * D; i += 128) {
        int r = i >> 6, c = i & 63;
        wsh[r * LDW + c] = __float2half(W[i]);
    }
    for (int i = tid; i < D * D; i += 128) {
        int r = i >> 6, c = i & 63;
        int row = blockIdx.x * 64 + r;
        float v = (row < N_NODES) ? in[(size_t)row * D + c] : 0.f;
        ash[r * LDW + c] = __float2half(v);
    }
    __syncthreads();

    int warp = tid >> 5;
    int row0 = blockIdx.x * 64 + warp * 16;
    if (row0 < N_NODES) {
        wmma::fragment<wmma::accumulator, 16, 16, 16, float> acc[4];
#pragma unroll
        for (int n = 0; n < 4; n++) wmma::fill_fragment(acc[n], 0.0f);
#pragma unroll
        for (int k = 0; k < 4; k++) {
            wmma::fragment<wmma::matrix_a, 16, 16, 16, __half, wmma::row_major> a;
            wmma::load_matrix_sync(a, ash + (warp * 16) * LDW + k * 16, LDW);
#pragma unroll
            for (int n = 0; n < 4; n++) {
                wmma::fragment<wmma::matrix_b, 16, 16, 16, __half, wmma::row_major> b;
                wmma::load_matrix_sync(b, wsh + (k * 16) * LDW + n * 16, LDW);
                wmma::mma_sync(acc[n], a, b, acc[n]);
            }
        }
#pragma unroll
        for (int n = 0; n < 4; n++)
            wmma::store_matrix_sync(osh + (warp * 16) * LDW + n * 16, acc[n], LDW, wmma::mem_row_major);
    }
    __syncthreads();
    gemm_epilogue(osh, out, blockIdx.x * 64, tid);
}

// ------- gather v3: 8 lanes/node, LDG.128 per edge, redundant index loads ----
// out_n = relu( dinv_n * (sum_{e:dst=n} h'[src_e] + h'[n]) + b )
__device__ __forceinline__ void acc8_add(float acc[8], float4 raw) {
    __half2* hp = (__half2*)&raw;
#pragma unroll
    for (int q = 0; q < 4; q++) {
        float2 f = __half22float2(hp[q]);
        acc[2 * q + 0] += f.x;
        acc[2 * q + 1] += f.y;
    }
}

template <bool FUSE_POOL>
__global__ void __launch_bounds__(256) k_gather8(const __half* __restrict__ h,
                                                 const float* __restrict__ b,
                                                 __half* __restrict__ out,
                                                 const float* __restrict__ fcw) {
    int gt = blockIdx.x * blockDim.x + threadIdx.x;
    int node = gt >> 3;
    int c = gt & 7;          // this lane's 8-channel group (16 bytes)

    const float4* h4 = (const float4*)h;   // 8 float4 per row

    float acc[8];
    {
        float4 raw = h4[(size_t)node * 8 + c];   // self loop (pre-scaled)
        __half2* hp = (__half2*)&raw;
#pragma unroll
        for (int q = 0; q < 4; q++) {
            float2 f = __half22float2(hp[q]);
            acc[2 * q + 0] = f.x;
            acc[2 * q + 1] = f.y;
        }
    }

    int e0 = g_rowstart[node];
    int e1 = g_rowstart[node + 1];
    int e = e0;
    for (; e + 3 < e1; e += 4) {
        int s0 = g_csrc[e];
        int s1 = g_csrc[e + 1];
        int s2 = g_csrc[e + 2];
        int s3 = g_csrc[e + 3];
        float4 r0 = h4[(size_t)s0 * 8 + c];
        float4 r1 = h4[(size_t)s1 * 8 + c];
        float4 r2 = h4[(size_t)s2 * 8 + c];
        float4 r3 = h4[(size_t)s3 * 8 + c];
        acc8_add(acc, r0);
        acc8_add(acc, r1);
        acc8_add(acc, r2);
        acc8_add(acc, r3);
    }
    for (; e < e1; e++) {
        float4 r = h4[(size_t)g_csrc[e] * 8 + c];
        acc8_add(acc, r);
    }

    float di = g_dinv[node];
    float o[8];
    const float4* bb = (const float4*)(b + c * 8);
    float4 b0 = bb[0], b1 = bb[1];
    o[0] = fmaxf(acc[0] * di + b0.x, 0.f);
    o[1] = fmaxf(acc[1] * di + b0.y, 0.f);
    o[2] = fmaxf(acc[2] * di + b0.z, 0.f);
    o[3] = fmaxf(acc[3] * di + b0.w, 0.f);
    o[4] = fmaxf(acc[4] * di + b1.x, 0.f);
    o[5] = fmaxf(acc[5] * di + b1.y, 0.f);
    o[6] = fmaxf(acc[6] * di + b1.z, 0.f);
    o[7] = fmaxf(acc[7] * di + b1.w, 0.f);

    if (FUSE_POOL) {
        int lane = threadIdx.x & 31;
        unsigned gmask = 0xffu << (lane & 24);   // my 8-lane group
        const float4* ww = (const float4*)(fcw + c * 8);
        float4 w0 = ww[0], w1 = ww[1];
        float dot = o[0] * w0.x + o[1] * w0.y + o[2] * w0.z + o[3] * w0.w
                  + o[4] * w1.x + o[5] * w1.y + o[6] * w1.z + o[7] * w1.w;
#pragma unroll
        for (int off = 4; off > 0; off >>= 1)
            dot += __shfl_down_sync(gmask, dot, off, 8);
        if (c == 0) g_nodedot[node] = dot;
    } else {
        __half2 p0 = __floats2half2_rn(o[0], o[1]);
        __half2 p1 = __floats2half2_rn(o[2], o[3]);
        __half2 p2 = __floats2half2_rn(o[4], o[5]);
        __half2 p3 = __floats2half2_rn(o[6], o[7]);
        uint4 u;
        u.x = *(unsigned*)&p0; u.y = *(unsigned*)&p1;
        u.z = *(unsigned*)&p2; u.w = *(unsigned*)&p3;
        ((uint4*)out)[(size_t)node * 8 + c] = u;
    }
}

// ------- pool + head: one block per graph over per-node scalars --------------
__global__ void __launch_bounds__(256) k_pool_graph(const float* __restrict__ fcb,
                                                    const int* __restrict__ batch,
                                                    float* __restrict__ out) {
    __shared__ int bounds[2];
    __shared__ float red[256 / 32];
    int tid = threadIdx.x;
    int g = blockIdx.x;
    if (tid == 0 || tid == 1) {
        int key = g + tid;
        int lo = 0, hi = N_NODES;
        while (lo < hi) {
            int mid = (lo + hi) >> 1;
            if (batch[mid] < key) lo = mid + 1; else hi = mid;
        }
        bounds[tid] = lo;
    }
    __syncthreads();
    int start = bounds[0], end = bounds[1];

    float s = 0.f;
    for (int i = start + tid; i < end; i += 256) s += g_nodedot[i];
#pragma unroll
    for (int off = 16; off > 0; off >>= 1)
        s += __shfl_down_sync(0xffffffffu, s, off);
    if ((tid & 31) == 0) red[tid >> 5] = s;
    __syncthreads();
    if (tid == 0) {
        float tot = 0.f;
#pragma unroll
        for (int wi = 0; wi < 256 / 32; wi++) tot += red[wi];
        int cnt = end - start;
        out[g] = tot / fmaxf((float)cnt, 1.f) + fcb[0];
    }
}

// ---------------- launch ------------------------------------------------------
extern "C" void kernel_launch(void* const* d_in, const int* in_sizes, int n_in,
                              void* d_out, int out_size) {
    const float* x     = (const float*)d_in[0];
    const int*   ei    = (const int*)  d_in[1];
    const int*   batch = (const int*)  d_in[2];
    const float* w0    = (const float*)d_in[3];
    const float* b0    = (const float*)d_in[4];
    const float* w1    = (const float*)d_in[5];
    const float* b1    = (const float*)d_in[6];
    const float* w2    = (const float*)d_in[7];
    const float* b2    = (const float*)d_in[8];
    const float* fcw   = (const float*)d_in[9];
    const float* fcb   = (const float*)d_in[10];
    float* out = (float*)d_out;

    __half *h, *t0, *t1;
    void *p_dege;
    cudaGetSymbolAddress((void**)&h,  g_h);
    cudaGetSymbolAddress((void**)&t0, g_t0);
    cudaGetSymbolAddress((void**)&t1, g_t1);
    cudaGetSymbolAddress(&p_dege, g_dege);

    const int TB = 256;
    int nb_nodes  = (N_NODES + TB - 1) / TB;           // 391
    int nb_edge4  = (N_EDGES / 4 + TB - 1) / TB;       // 1250
    int nb_gemm16 = (N_NODES + 127) / 128;             // 782
    int nb_gemm32 = (N_NODES + 63) / 64;               // 1563
    int nb_gath   = (N_NODES * 8) / TB;                // 3125 exact

    cudaMemsetAsync(p_dege, 0, N_NODES * sizeof(int));

    // CSR build (once per call, reused by all 3 layers)
    k_deg  <<<nb_edge4, TB>>>(ei);
    k_scan1<<<N_SCANBLK, SCAN_B>>>();
    k_scan2<<<1, 128>>>();
    k_scan3<<<nb_nodes, TB>>>();
    k_fill <<<nb_edge4, TB>>>(ei);

    // layer 1
    k_gemm_f32<<<nb_gemm32, 128>>>(x, w0, h);
    k_gather8<false><<<nb_gath, TB>>>(h, b0, t0, nullptr);
    // layer 2
    k_gemm_f16<<<nb_gemm16, 256>>>(t0, w1, h);
    k_gather8<false><<<nb_gath, TB>>>(h, b1, t1, nullptr);
    // layer 3 (gather fused with pool dot; writes per-node scalar)
    k_gemm_f16<<<nb_gemm16, 256>>>(t1, w2, h);
    k_gather8<true><<<nb_gath, TB>>>(h, b2, nullptr, fcw);

    // pool + head
    k_pool_graph<<<N_GRAPHS, 256>>>(fcb, batch, out);
}

// round 8
// speedup vs baseline: 1.0926x; 1.0528x over previous
#include <cuda_runtime.h>
#include <cuda_fp16.h>
#include <mma.h>
using namespace nvcuda;

#define N_NODES   100000
#define N_EDGES   1280000
#define D         64
#define N_GRAPHS  512
#define SCAN_B    1024
#define N_SCANBLK ((N_NODES + SCAN_B - 1) / SCAN_B)   // 98

// ---------------- scratch (device globals; no cudaMalloc allowed) -----------
__device__ __half g_h  [N_NODES * D];   // GEMM output, pre-scaled by dinv[row]
__device__ __half g_t0 [N_NODES * D];
__device__ __half g_t1 [N_NODES * D];
__device__ float  g_dinv[N_NODES];
__device__ int    g_dege[N_NODES];
__device__ int    g_rowstart[N_NODES + 1];
__device__ int    g_bsums[128];
__device__ int    g_csrc [N_EDGES];
__device__ int    g_rank [N_EDGES];
__device__ float  g_nodedot[N_NODES];

// ---------------- setup kernels ---------------------------------------------
__global__ void k_deg(const int* __restrict__ ei) {
    int t = blockIdx.x * blockDim.x + threadIdx.x;
    if (t < N_EDGES / 4) {
        int4 d4 = ((const int4*)(ei + N_EDGES))[t];
        int4 r;
        r.x = atomicAdd(&g_dege[d4.x], 1);
        r.y = atomicAdd(&g_dege[d4.y], 1);
        r.z = atomicAdd(&g_dege[d4.z], 1);
        r.w = atomicAdd(&g_dege[d4.w], 1);
        ((int4*)g_rank)[t] = r;
    }
}

__global__ void k_scan1() {
    __shared__ int sh[SCAN_B];
    int tid = threadIdx.x;
    int i = blockIdx.x * SCAN_B + tid;
    int v = (i < N_NODES) ? g_dege[i] : 0;
    sh[tid] = v;
    __syncthreads();
    for (int off = 1; off < SCAN_B; off <<= 1) {
        int t = 0;
        if (tid >= off) t = sh[tid - off];
        __syncthreads();
        sh[tid] += t;
        __syncthreads();
    }
    int incl = sh[tid];
    if (i < N_NODES) g_rowstart[i] = incl - v;   // exclusive
    if (tid == SCAN_B - 1) g_bsums[blockIdx.x] = incl;
}

__global__ void k_scan2() {
    __shared__ int sh[128];
    int tid = threadIdx.x;
    int v = (tid < N_SCANBLK) ? g_bsums[tid] : 0;
    sh[tid] = v;
    __syncthreads();
    for (int off = 1; off < 128; off <<= 1) {
        int t = 0;
        if (tid >= off) t = sh[tid - off];
        __syncthreads();
        sh[tid] += t;
        __syncthreads();
    }
    if (tid < N_SCANBLK) g_bsums[tid] = sh[tid] - v;   // exclusive
    if (tid == N_SCANBLK - 1) g_rowstart[N_NODES] = sh[tid];
}

__global__ void k_scan3() {
    int i = blockIdx.x * blockDim.x + threadIdx.x;
    if (i < N_NODES) {
        g_rowstart[i] = g_rowstart[i] + g_bsums[i / SCAN_B];
        g_dinv[i] = rsqrtf((float)(g_dege[i] + 1));   // +1 self loop
    }
}

__global__ void k_fill(const int* __restrict__ ei) {
    int t = blockIdx.x * blockDim.x + threadIdx.x;
    if (t < N_EDGES / 4) {
        int4 s4 = ((const int4*)ei)[t];
        int4 d4 = ((const int4*)(ei + N_EDGES))[t];
        int4 r4 = ((const int4*)g_rank)[t];
        g_csrc[g_rowstart[d4.x] + r4.x] = s4.x;
        g_csrc[g_rowstart[d4.y] + r4.y] = s4.y;
        g_csrc[g_rowstart[d4.z] + r4.z] = s4.z;
        g_csrc[g_rowstart[d4.w] + r4.w] = s4.w;
    }
}

// ---------------- tensor-core GEMM: out[row] = dinv[row]*(in[row] @ W), fp16 out
#define LDW 72   // padded leading dim to dodge smem bank conflicts

__device__ __forceinline__ void gemm_epilogue(const float* osh, __half* __restrict__ out,
                                              int blockRow0, int tid) {
    int r = tid >> 1;
    int cbase = (tid & 1) * 32;
    int row = blockRow0 + r;
    if (row >= N_NODES) return;
    float s = g_dinv[row];
    uint4* orow = (uint4*)(out + (size_t)row * D + cbase);
    const float* src = osh + r * LDW + cbase;
#pragma unroll
    for (int q = 0; q < 4; q++) {
        __half2 p0 = __floats2half2_rn(src[q * 8 + 0] * s, src[q * 8 + 1] * s);
        __half2 p1 = __floats2half2_rn(src[q * 8 + 2] * s, src[q * 8 + 3] * s);
        __half2 p2 = __floats2half2_rn(src[q * 8 + 4] * s, src[q * 8 + 5] * s);
        __half2 p3 = __floats2half2_rn(src[q * 8 + 6] * s, src[q * 8 + 7] * s);
        uint4 u;
        u.x = *(unsigned*)&p0; u.y = *(unsigned*)&p1;
        u.z = *(unsigned*)&p2; u.w = *(unsigned*)&p3;
        orow[q] = u;
    }
}

__global__ void __launch_bounds__(256) k_gemm_f16(const __half* __restrict__ in,
                                                  const float* __restrict__ W,
                                                  __half* __restrict__ out) {
    __shared__ __half wsh[D * LDW];
    __shared__ float  osh[128 * LDW];
    int tid = threadIdx.x;
    for (int i = tid; i < D * D; i += 256) {
        int r = i >> 6, c = i & 63;
        wsh[r * LDW + c] = __float2half(W[i]);
    }
    __syncthreads();

    int warp = tid >> 5;
    int row0 = blockIdx.x * 128 + warp * 16;
    if (row0 < N_NODES) {
        wmma::fragment<wmma::accumulator, 16, 16, 16, float> acc[4];
#pragma unroll
        for (int n = 0; n < 4; n++) wmma::fill_fragment(acc[n], 0.0f);
#pragma unroll
        for (int k = 0; k < 4; k++) {
            wmma::fragment<wmma::matrix_a, 16, 16, 16, __half, wmma::row_major> a;
            wmma::load_matrix_sync(a, in + (size_t)row0 * D + k * 16, D);
#pragma unroll
            for (int n = 0; n < 4; n++) {
                wmma::fragment<wmma::matrix_b, 16, 16, 16, __half, wmma::row_major> b;
                wmma::load_matrix_sync(b, wsh + (k * 16) * LDW + n * 16, LDW);
                wmma::mma_sync(acc[n], a, b, acc[n]);
            }
        }
#pragma unroll
        for (int n = 0; n < 4; n++)
            wmma::store_matrix_sync(osh + (warp * 16) * LDW + n * 16, acc[n], LDW, wmma::mem_row_major);
    }
    __syncthreads();
    gemm_epilogue(osh, out, blockIdx.x * 128, tid);
}

__global__ void __launch_bounds__(128) k_gemm_f32(const float* __restrict__ in,
                                                  const float* __restrict__ W,
                                                  __half* __restrict__ out) {
    __shared__ __half wsh[D * LDW];
    __shared__ __half ash[D * LDW];
    __shared__ float  osh[D * LDW];
    int tid = threadIdx.x;
    for (int i = tid; i < D * D; i += 128) {
        int r = i >> 6, c = i & 63;
        wsh[r * LDW + c] = __float2half(W[i]);
    }
    for (int i = tid; i < D * D; i += 128) {
        int r = i >> 6, c = i & 63;
        int row = blockIdx.x * 64 + r;
        float v = (row < N_NODES) ? in[(size_t)row * D + c] : 0.f;
        ash[r * LDW + c] = __float2half(v);
    }
    __syncthreads();

    int warp = tid >> 5;
    int row0 = blockIdx.x * 64 + warp * 16;
    if (row0 < N_NODES) {
        wmma::fragment<wmma::accumulator, 16, 16, 16, float> acc[4];
#pragma unroll
        for (int n = 0; n < 4; n++) wmma::fill_fragment(acc[n], 0.0f);
#pragma unroll
        for (int k = 0; k < 4; k++) {
            wmma::fragment<wmma::matrix_a, 16, 16, 16, __half, wmma::row_major> a;
            wmma::load_matrix_sync(a, ash + (warp * 16) * LDW + k * 16, LDW);
#pragma unroll
            for (int n = 0; n < 4; n++) {
                wmma::fragment<wmma::matrix_b, 16, 16, 16, __half, wmma::row_major> b;
                wmma::load_matrix_sync(b, wsh + (k * 16) * LDW + n * 16, LDW);
                wmma::mma_sync(acc[n], a, b, acc[n]);
            }
        }
#pragma unroll
        for (int n = 0; n < 4; n++)
            wmma::store_matrix_sync(osh + (warp * 16) * LDW + n * 16, acc[n], LDW, wmma::mem_row_major);
    }
    __syncthreads();
    gemm_epilogue(osh, out, blockIdx.x * 64, tid);
}

// ------- gather v4: 8 lanes/node, LDG.128 per edge, half2-tree accumulate ----
// out_n = relu( dinv_n * (sum_{e:dst=n} h'[src_e] + h'[n]) + b )
template <bool FUSE_POOL>
__global__ void __launch_bounds__(256) k_gather8(const __half* __restrict__ h,
                                                 const float* __restrict__ b,
                                                 __half* __restrict__ out,
                                                 const float* __restrict__ fcw) {
    int gt = blockIdx.x * blockDim.x + threadIdx.x;
    int node = gt >> 3;
    int c = gt & 7;          // this lane's 8-channel group (16 bytes)

    const float4* h4 = (const float4*)h;   // 8 float4 per row

    float acc[8];
    {
        float4 raw = h4[(size_t)node * 8 + c];   // self loop (pre-scaled)
        __half2* hp = (__half2*)&raw;
#pragma unroll
        for (int q = 0; q < 4; q++) {
            float2 f = __half22float2(hp[q]);
            acc[2 * q + 0] = f.x;
            acc[2 * q + 1] = f.y;
        }
    }

    int e0 = g_rowstart[node];
    int e1 = g_rowstart[node + 1];
    int e = e0;
    for (; e + 3 < e1; e += 4) {
        int s0 = g_csrc[e];
        int s1 = g_csrc[e + 1];
        int s2 = g_csrc[e + 2];
        int s3 = g_csrc[e + 3];
        float4 r0 = h4[(size_t)s0 * 8 + c];
        float4 r1 = h4[(size_t)s1 * 8 + c];
        float4 r2 = h4[(size_t)s2 * 8 + c];
        float4 r3 = h4[(size_t)s3 * 8 + c];
        __half2* p0 = (__half2*)&r0;
        __half2* p1 = (__half2*)&r1;
        __half2* p2 = (__half2*)&r2;
        __half2* p3 = (__half2*)&r3;
        // pairwise half2 tree: 2 fp16 roundings per element, fp32 running sum
#pragma unroll
        for (int q = 0; q < 4; q++) {
            __half2 a01 = __hadd2(p0[q], p1[q]);
            __half2 a23 = __hadd2(p2[q], p3[q]);
            __half2 s4 = __hadd2(a01, a23);
            float2 f = __half22float2(s4);
            acc[2 * q + 0] += f.x;
            acc[2 * q + 1] += f.y;
        }
    }
    for (; e < e1; e++) {
        float4 r = h4[(size_t)g_csrc[e] * 8 + c];
        __half2* hp = (__half2*)&r;
#pragma unroll
        for (int q = 0; q < 4; q++) {
            float2 f = __half22float2(hp[q]);
            acc[2 * q + 0] += f.x;
            acc[2 * q + 1] += f.y;
        }
    }

    float di = g_dinv[node];
    float o[8];
    const float4* bb = (const float4*)(b + c * 8);
    float4 b0 = bb[0], b1 = bb[1];
    o[0] = fmaxf(acc[0] * di + b0.x, 0.f);
    o[1] = fmaxf(acc[1] * di + b0.y, 0.f);
    o[2] = fmaxf(acc[2] * di + b0.z, 0.f);
    o[3] = fmaxf(acc[3] * di + b0.w, 0.f);
    o[4] = fmaxf(acc[4] * di + b1.x, 0.f);
    o[5] = fmaxf(acc[5] * di + b1.y, 0.f);
    o[6] = fmaxf(acc[6] * di + b1.z, 0.f);
    o[7] = fmaxf(acc[7] * di + b1.w, 0.f);

    if (FUSE_POOL) {
        int lane = threadIdx.x & 31;
        unsigned gmask = 0xffu << (lane & 24);   // my 8-lane group
        const float4* ww = (const float4*)(fcw + c * 8);
        float4 w0 = ww[0], w1 = ww[1];
        float dot = o[0] * w0.x + o[1] * w0.y + o[2] * w0.z + o[3] * w0.w
                  + o[4] * w1.x + o[5] * w1.y + o[6] * w1.z + o[7] * w1.w;
#pragma unroll
        for (int off = 4; off > 0; off >>= 1)
            dot += __shfl_down_sync(gmask, dot, off, 8);
        if (c == 0) g_nodedot[node] = dot;
    } else {
        __half2 p0 = __floats2half2_rn(o[0], o[1]);
        __half2 p1 = __floats2half2_rn(o[2], o[3]);
        __half2 p2 = __floats2half2_rn(o[4], o[5]);
        __half2 p3 = __floats2half2_rn(o[6], o[7]);
        uint4 u;
        u.x = *(unsigned*)&p0; u.y = *(unsigned*)&p1;
        u.z = *(unsigned*)&p2; u.w = *(unsigned*)&p3;
        ((uint4*)out)[(size_t)node * 8 + c] = u;
    }
}

// ------- pool + head: one block per graph over per-node scalars --------------
__global__ void __launch_bounds__(256) k_pool_graph(const float* __restrict__ fcb,
                                                    const int* __restrict__ batch,
                                                    float* __restrict__ out) {
    __shared__ int bounds[2];
    __shared__ float red[256 / 32];
    int tid = threadIdx.x;
    int g = blockIdx.x;
    if (tid == 0 || tid == 1) {
        int key = g + tid;
        int lo = 0, hi = N_NODES;
        while (lo < hi) {
            int mid = (lo + hi) >> 1;
            if (batch[mid] < key) lo = mid + 1; else hi = mid;
        }
        bounds[tid] = lo;
    }
    __syncthreads();
    int start = bounds[0], end = bounds[1];

    float s = 0.f;
    for (int i = start + tid; i < end; i += 256) s += g_nodedot[i];
#pragma unroll
    for (int off = 16; off > 0; off >>= 1)
        s += __shfl_down_sync(0xffffffffu, s, off);
    if ((tid & 31) == 0) red[tid >> 5] = s;
    __syncthreads();
    if (tid == 0) {
        float tot = 0.f;
#pragma unroll
        for (int wi = 0; wi < 256 / 32; wi++) tot += red[wi];
        int cnt = end - start;
        out[g] = tot / fmaxf((float)cnt, 1.f) + fcb[0];
    }
}

// ---------------- launch ------------------------------------------------------
extern "C" void kernel_launch(void* const* d_in, const int* in_sizes, int n_in,
                              void* d_out, int out_size) {
    const float* x     = (const float*)d_in[0];
    const int*   ei    = (const int*)  d_in[1];
    const int*   batch = (const int*)  d_in[2];
    const float* w0    = (const float*)d_in[3];
    const float* b0    = (const float*)d_in[4];
    const float* w1    = (const float*)d_in[5];
    const float* b1    = (const float*)d_in[6];
    const float* w2    = (const float*)d_in[7];
    const float* b2    = (const float*)d_in[8];
    const float* fcw   = (const float*)d_in[9];
    const float* fcb   = (const float*)d_in[10];
    float* out = (float*)d_out;

    __half *h, *t0, *t1;
    void *p_dege;
    cudaGetSymbolAddress((void**)&h,  g_h);
    cudaGetSymbolAddress((void**)&t0, g_t0);
    cudaGetSymbolAddress((void**)&t1, g_t1);
    cudaGetSymbolAddress(&p_dege, g_dege);

    const int TB = 256;
    int nb_nodes  = (N_NODES + TB - 1) / TB;           // 391
    int nb_edge4  = (N_EDGES / 4 + TB - 1) / TB;       // 1250
    int nb_gemm16 = (N_NODES + 127) / 128;             // 782
    int nb_gemm32 = (N_NODES + 63) / 64;               // 1563
    int nb_gath   = (N_NODES * 8) / TB;                // 3125 exact

    cudaMemsetAsync(p_dege, 0, N_NODES * sizeof(int));

    // CSR build (once per call, reused by all 3 layers)
    k_deg  <<<nb_edge4, TB>>>(ei);
    k_scan1<<<N_SCANBLK, SCAN_B>>>();
    k_scan2<<<1, 128>>>();
    k_scan3<<<nb_nodes, TB>>>();
    k_fill <<<nb_edge4, TB>>>(ei);

    // layer 1
    k_gemm_f32<<<nb_gemm32, 128>>>(x, w0, h);
    k_gather8<false><<<nb_gath, TB>>>(h, b0, t0, nullptr);
    // layer 2
    k_gemm_f16<<<nb_gemm16, 256>>>(t0, w1, h);
    k_gather8<false><<<nb_gath, TB>>>(h, b1, t1, nullptr);
    // layer 3 (gather fused with pool dot; writes per-node scalar)
    k_gemm_f16<<<nb_gemm16, 256>>>(t1, w2, h);
    k_gather8<true><<<nb_gath, TB>>>(h, b2, nullptr, fcw);

    // pool + head
    k_pool_graph<<<N_GRAPHS, 256>>>(fcb, batch, out);
}